// round 3
// baseline (speedup 1.0000x reference)
#include <cuda_runtime.h>
#include <cuda_bf16.h>
#include <cstdint>

// Problem dims
#define BB 128
#define TT 256
#define HH 1024
#define VV 4096
#define K3 3072          // split-K stacked (hi|hi|lo)
#define K6 6144

// ---------------- static device scratch ----------------
__device__ __align__(128) __nv_bfloat16 g_W0p[1024 * 3072];        // Whh0 stacked [hi|lo|hi]
__device__ __align__(128) __nv_bfloat16 g_W1p[1024 * 6144];        // [Wih1 stacked | Whh1 stacked]
__device__ __align__(128) __nv_bfloat16 g_Wfcp[4096 * 3072];       // Wfc stacked
__device__ __align__(128) float g_bias0[1024];
__device__ __align__(128) float g_bias1[1024];
__device__ __align__(128) __nv_bfloat16 g_h0buf[2][BB * K3];       // ping-pong h0 split [hi|hi|lo]
__device__ __align__(128) __nv_bfloat16 g_h1zero[BB * K3];         // zeros (h1 at t=-1)
__device__ __align__(128) __nv_bfloat16 g_H1S[TT][BB * K3];        // all h1 split, FC input (192MB)
__device__ __align__(128) float g_part0[6][BB * 1024];
__device__ __align__(128) float g_part1[12][BB * 1024];
__device__ int g_ctr[2][8];

// ---------------- helpers ----------------
__device__ __forceinline__ void split2(float w, __nv_bfloat16& hi, __nv_bfloat16& lo) {
    hi = __float2bfloat16(w);
    lo = __float2bfloat16(w - __bfloat162float(hi));
}

// 128x128 CTA tile GEMM core: C += A[128,K] * B[128,K]^T, bf16 in, fp32 accum.
// A row-major (lda), B row-major-by-N (ldb, K contiguous) == mma col-major B.
// 256 threads, 8 warps as 2(M)x4(N): warp tile 64x32.
__device__ __forceinline__ void gemm_core(
    const __nv_bfloat16* __restrict__ A, int lda,
    const __nv_bfloat16* __restrict__ B, int ldb,
    int nChunks, __nv_bfloat16* As, __nv_bfloat16* Bs, float acc[4][4][4])
{
    const int tid  = threadIdx.x;
    const int warp = tid >> 5, lane = tid & 31;
    const int gid  = lane >> 2, tig = lane & 3;
    const int wm   = (warp & 1) << 6;   // 0 / 64
    const int wn   = (warp >> 1) << 5;  // 0 / 32 / 64 / 96
    const int r0   = tid >> 2;          // 0..63
    const int s0   = (tid & 3) << 3;    // 0,8,16,24 (halves)

    const __nv_bfloat16* pa0 = A + (size_t)r0 * lda + s0;
    const __nv_bfloat16* pa1 = A + (size_t)(r0 + 64) * lda + s0;
    const __nv_bfloat16* pb0 = B + (size_t)r0 * ldb + s0;
    const __nv_bfloat16* pb1 = B + (size_t)(r0 + 64) * ldb + s0;

    uint4 ra0 = *reinterpret_cast<const uint4*>(pa0);
    uint4 ra1 = *reinterpret_cast<const uint4*>(pa1);
    uint4 rb0 = *reinterpret_cast<const uint4*>(pb0);
    uint4 rb1 = *reinterpret_cast<const uint4*>(pb1);

    const unsigned* Aw = reinterpret_cast<const unsigned*>(As);
    const unsigned* Bw = reinterpret_cast<const unsigned*>(Bs);

    for (int kt = 0; kt < nChunks; ++kt) {
        __syncthreads();
        *reinterpret_cast<uint4*>(As + r0 * 40 + s0)        = ra0;
        *reinterpret_cast<uint4*>(As + (r0 + 64) * 40 + s0) = ra1;
        *reinterpret_cast<uint4*>(Bs + r0 * 40 + s0)        = rb0;
        *reinterpret_cast<uint4*>(Bs + (r0 + 64) * 40 + s0) = rb1;
        __syncthreads();
        if (kt + 1 < nChunks) {
            const int ko = (kt + 1) << 5;
            ra0 = *reinterpret_cast<const uint4*>(pa0 + ko);
            ra1 = *reinterpret_cast<const uint4*>(pa1 + ko);
            rb0 = *reinterpret_cast<const uint4*>(pb0 + ko);
            rb1 = *reinterpret_cast<const uint4*>(pb1 + ko);
        }
#pragma unroll
        for (int ks = 0; ks < 2; ++ks) {
            const int kw = ks << 3;  // word offset for k=0 / k=16
            unsigned af[4][4], bfr[4][2];
#pragma unroll
            for (int mi = 0; mi < 4; ++mi) {
                const int rb = (wm + (mi << 4) + gid) * 20 + kw + tig;
                af[mi][0] = Aw[rb];
                af[mi][1] = Aw[rb + 160];
                af[mi][2] = Aw[rb + 4];
                af[mi][3] = Aw[rb + 164];
            }
#pragma unroll
            for (int ni = 0; ni < 4; ++ni) {
                const int nb = (wn + (ni << 3) + gid) * 20 + kw + tig;
                bfr[ni][0] = Bw[nb];
                bfr[ni][1] = Bw[nb + 4];
            }
#pragma unroll
            for (int mi = 0; mi < 4; ++mi)
#pragma unroll
                for (int ni = 0; ni < 4; ++ni) {
                    asm volatile(
                        "mma.sync.aligned.m16n8k16.row.col.f32.bf16.bf16.f32 "
                        "{%0,%1,%2,%3},{%4,%5,%6,%7},{%8,%9},{%0,%1,%2,%3};\n"
                        : "+f"(acc[mi][ni][0]), "+f"(acc[mi][ni][1]),
                          "+f"(acc[mi][ni][2]), "+f"(acc[mi][ni][3])
                        : "r"(af[mi][0]), "r"(af[mi][1]), "r"(af[mi][2]), "r"(af[mi][3]),
                          "r"(bfr[ni][0]), "r"(bfr[ni][1]));
                }
        }
    }
}

// ---------------- init / prep ----------------
__global__ void init_kernel() {
    int i = blockIdx.x * blockDim.x + threadIdx.x;  // 0..393215
    if (i < BB * K3) {
        g_h0buf[0][i] = __float2bfloat16(0.f);
        g_h1zero[i]   = __float2bfloat16(0.f);
    }
    if (i < 16) reinterpret_cast<int*>(g_ctr)[i] = 0;
}

__global__ void prep_kernel(const float* __restrict__ Whh0,
                            const float* __restrict__ bih0, const float* __restrict__ bhh0,
                            const float* __restrict__ Wih1, const float* __restrict__ Whh1,
                            const float* __restrict__ bih1, const float* __restrict__ bhh1,
                            const float* __restrict__ Wfc)
{
    const int NFC = 4096 * 1024;
    for (int i = blockIdx.x * blockDim.x + threadIdx.x; i < NFC; i += gridDim.x * blockDim.x) {
        int j = i >> 10, k = i & 1023;
        __nv_bfloat16 hi, lo;
        split2(Wfc[i], hi, lo);
        g_Wfcp[(size_t)j * 3072 + k]        = hi;
        g_Wfcp[(size_t)j * 3072 + 1024 + k] = lo;
        g_Wfcp[(size_t)j * 3072 + 2048 + k] = hi;
        if (i < 1024 * 1024) {
            split2(Whh0[i], hi, lo);
            g_W0p[(size_t)j * 3072 + k]        = hi;
            g_W0p[(size_t)j * 3072 + 1024 + k] = lo;
            g_W0p[(size_t)j * 3072 + 2048 + k] = hi;
            split2(Wih1[i], hi, lo);
            g_W1p[(size_t)j * 6144 + k]        = hi;
            g_W1p[(size_t)j * 6144 + 1024 + k] = lo;
            g_W1p[(size_t)j * 6144 + 2048 + k] = hi;
            split2(Whh1[i], hi, lo);
            g_W1p[(size_t)j * 6144 + 3072 + k]        = hi;
            g_W1p[(size_t)j * 6144 + 3072 + 1024 + k] = lo;
            g_W1p[(size_t)j * 6144 + 3072 + 2048 + k] = hi;
        }
        if (i < 1024) {
            g_bias0[i] = bih0[i] + bhh0[i];
            g_bias1[i] = bih1[i] + bhh1[i];
        }
    }
}

// ---------------- recurrence step (pipelined: L0 at t=s, L1 at t=s-1) ----------------
__global__ __launch_bounds__(256) void step_kernel(const float* __restrict__ x,
                                                   const float* __restrict__ Wih0, int s)
{
    __shared__ __align__(16) __nv_bfloat16 As[128 * 40];
    __shared__ __align__(16) __nv_bfloat16 Bs[128 * 40];
    float acc[4][4][4];
#pragma unroll
    for (int a = 0; a < 4; ++a)
#pragma unroll
        for (int b = 0; b < 4; ++b)
#pragma unroll
            for (int c = 0; c < 4; ++c) acc[a][b][c] = 0.f;

    const int bidx = blockIdx.x;
    int layer, tile, split, nsplit, ldb;
    const __nv_bfloat16 *A, *Bp;

    if (bidx < 48) {                 // layer 0: 8 tiles x 6 splits
        if (s == 256) return;
        layer = 0; tile = bidx / 6; split = bidx % 6; nsplit = 6; ldb = 3072;
        A  = g_h0buf[s & 1] + split * 512;
        Bp = g_W0p + (size_t)tile * 128 * 3072 + split * 512;
    } else {                          // layer 1: 8 tiles x 12 splits
        if (s == 0) return;
        layer = 1; const int j = bidx - 48; tile = j / 12; split = j % 12; nsplit = 12; ldb = 6144;
        const int u = s - 1;
        if (split < 6) A = g_h0buf[s & 1] + split * 512;               // h0(t=u)
        else {
            const __nv_bfloat16* hprev = (u == 0) ? g_h1zero : g_H1S[u - 1];
            A = hprev + (split - 6) * 512;                              // h1(t=u-1)
        }
        Bp = g_W1p + (size_t)tile * 128 * 6144 +
             ((split < 6) ? split * 512 : 3072 + (split - 6) * 512);
    }

    gemm_core(A, 3072, Bp, ldb, 16, As, Bs, acc);

    // write partial tile
    float* part = (layer == 0) ? g_part0[split] : g_part1[split];
    {
        const int lane = threadIdx.x & 31, warp = threadIdx.x >> 5;
        const int gid = lane >> 2, tig = lane & 3;
        const int wm = (warp & 1) << 6, wn = (warp >> 1) << 5;
#pragma unroll
        for (int mi = 0; mi < 4; ++mi)
#pragma unroll
            for (int ni = 0; ni < 4; ++ni) {
                const int row = wm + (mi << 4) + gid;
                const int col = tile * 128 + wn + (ni << 3) + 2 * tig;
                *reinterpret_cast<float2*>(&part[row * 1024 + col]) =
                    make_float2(acc[mi][ni][0], acc[mi][ni][1]);
                *reinterpret_cast<float2*>(&part[(row + 8) * 1024 + col]) =
                    make_float2(acc[mi][ni][2], acc[mi][ni][3]);
            }
    }

    __threadfence();
    __shared__ int lastFlag;
    if (threadIdx.x == 0) {
        const int old = atomicAdd(&g_ctr[layer][tile], 1);
        lastFlag = (old == nsplit - 1);
    }
    __syncthreads();
    if (!lastFlag) return;

    // last CTA per tile: reduce + bias (+ rank-1 x*W_ih0 for L0) + tanh + re-split
    if (layer == 0) {
        __nv_bfloat16* dst = g_h0buf[(s + 1) & 1];
        for (int i = threadIdx.x; i < 128 * 128; i += 256) {
            const int b = i >> 7, c = i & 127, g = tile * 128 + c;
            float v = g_bias0[g] + x[b * TT + s] * Wih0[g];
#pragma unroll
            for (int sp = 0; sp < 6; ++sp) v += __ldcg(&g_part0[sp][b * 1024 + g]);
            v = tanhf(v);
            __nv_bfloat16 hi, lo; split2(v, hi, lo);
            dst[b * K3 + g]        = hi;
            dst[b * K3 + 1024 + g] = hi;
            dst[b * K3 + 2048 + g] = lo;
        }
    } else {
        __nv_bfloat16* dst = g_H1S[s - 1];
        for (int i = threadIdx.x; i < 128 * 128; i += 256) {
            const int b = i >> 7, c = i & 127, g = tile * 128 + c;
            float v = g_bias1[g];
#pragma unroll
            for (int sp = 0; sp < 12; ++sp) v += __ldcg(&g_part1[sp][b * 1024 + g]);
            v = tanhf(v);
            __nv_bfloat16 hi, lo; split2(v, hi, lo);
            dst[b * K3 + g]        = hi;
            dst[b * K3 + 1024 + g] = hi;
            dst[b * K3 + 2048 + g] = lo;
        }
    }
    if (threadIdx.x == 0) g_ctr[layer][tile] = 0;  // ready for next launch / replay
}

// ---------------- trailing FC GEMM: out[b,t,v] = h1(t) . Wfc[v] + bfc[v] ----------------
__global__ __launch_bounds__(256) void fc_kernel(const float* __restrict__ bfc,
                                                 float* __restrict__ out)
{
    __shared__ __align__(16) __nv_bfloat16 As[128 * 40];
    __shared__ __align__(16) __nv_bfloat16 Bs[128 * 40];
    float acc[4][4][4];
#pragma unroll
    for (int a = 0; a < 4; ++a)
#pragma unroll
        for (int b = 0; b < 4; ++b)
#pragma unroll
            for (int c = 0; c < 4; ++c) acc[a][b][c] = 0.f;

    const int tn = blockIdx.x;   // 0..31 (V tiles)
    const int t  = blockIdx.y;   // 0..255 (time == M tile)
    const __nv_bfloat16* A  = g_H1S[t];
    const __nv_bfloat16* Bp = g_Wfcp + (size_t)tn * 128 * 3072;

    gemm_core(A, 3072, Bp, 3072, 96, As, Bs, acc);

    const int lane = threadIdx.x & 31, warp = threadIdx.x >> 5;
    const int gid = lane >> 2, tig = lane & 3;
    const int wm = (warp & 1) << 6, wn = (warp >> 1) << 5;
#pragma unroll
    for (int mi = 0; mi < 4; ++mi)
#pragma unroll
        for (int ni = 0; ni < 4; ++ni) {
            const int b   = wm + (mi << 4) + gid;          // batch row
            const int col = tn * 128 + wn + (ni << 3) + 2 * tig;
            const float bv0 = bfc[col], bv1 = bfc[col + 1];
            const size_t o0 = ((size_t)b * TT + t) * VV + col;
            const size_t o1 = ((size_t)(b + 8) * TT + t) * VV + col;
            *reinterpret_cast<float2*>(&out[o0]) =
                make_float2(acc[mi][ni][0] + bv0, acc[mi][ni][1] + bv1);
            *reinterpret_cast<float2*>(&out[o1]) =
                make_float2(acc[mi][ni][2] + bv0, acc[mi][ni][3] + bv1);
        }
}

// ---------------- final hidden states ----------------
__global__ void tail_kernel(float* __restrict__ out) {
    const int i = blockIdx.x * blockDim.x + threadIdx.x;  // 0 .. 2*B*H-1
    if (i >= 2 * BB * HH) return;
    const size_t base = (size_t)BB * TT * VV;
    if (i < BB * HH) {
        const int b = i >> 10, j = i & 1023;
        const __nv_bfloat16* src = g_h0buf[0] + b * K3;   // h0(255) lives in buf 0
        out[base + i] = __bfloat162float(src[j]) + __bfloat162float(src[2048 + j]);
    } else {
        const int k = i - BB * HH;
        const int b = k >> 10, j = k & 1023;
        const __nv_bfloat16* src = g_H1S[TT - 1] + b * K3;
        out[base + i] = __bfloat162float(src[j]) + __bfloat162float(src[2048 + j]);
    }
}

// ---------------- launch ----------------
extern "C" void kernel_launch(void* const* d_in, const int* in_sizes, int n_in,
                              void* d_out, int out_size)
{
    const float* x    = (const float*)d_in[0];
    const float* Wih0 = (const float*)d_in[1];
    const float* Whh0 = (const float*)d_in[2];
    const float* bih0 = (const float*)d_in[3];
    const float* bhh0 = (const float*)d_in[4];
    const float* Wih1 = (const float*)d_in[5];
    const float* Whh1 = (const float*)d_in[6];
    const float* bih1 = (const float*)d_in[7];
    const float* bhh1 = (const float*)d_in[8];
    const float* Wfc  = (const float*)d_in[9];
    const float* bfc  = (const float*)d_in[10];
    float* out = (float*)d_out;

    init_kernel<<<(BB * K3 + 255) / 256, 256>>>();
    prep_kernel<<<2048, 256>>>(Whh0, bih0, bhh0, Wih1, Whh1, bih1, bhh1, Wfc);

    for (int s = 0; s <= TT; ++s)
        step_kernel<<<144, 256>>>(x, Wih0, s);

    fc_kernel<<<dim3(32, 256), 256>>>(bfc, out);

    if (out_size >= BB * TT * VV + 2 * BB * HH)
        tail_kernel<<<(2 * BB * HH + 255) / 256, 256>>>(out);
}

// round 4
// speedup vs baseline: 1.2208x; 1.2208x over previous
#include <cuda_runtime.h>
#include <cuda_bf16.h>
#include <cstdint>

// Problem dims
#define BB 128
#define TT 256
#define HH 1024
#define VV 4096
#define K3 3072          // split-K stacked (hi|hi|lo)
#define K6 6144

// ---------------- static device scratch ----------------
__device__ __align__(128) __nv_bfloat16 g_W0p[1024 * 3072];        // Whh0 stacked [hi|lo|hi]
__device__ __align__(128) __nv_bfloat16 g_W1p[1024 * 6144];        // [Wih1 stacked | Whh1 stacked]
__device__ __align__(128) __nv_bfloat16 g_Wfcp[4096 * 3072];       // Wfc stacked
__device__ __align__(128) float g_bias0[1024];
__device__ __align__(128) float g_bias1[1024];
__device__ __align__(128) __nv_bfloat16 g_h0buf[2][BB * K3];       // ping-pong h0 split [hi|hi|lo]
__device__ __align__(128) __nv_bfloat16 g_h1zero[BB * K3];         // zeros (h1 at t=-1)
__device__ __align__(128) __nv_bfloat16 g_H1S[TT][BB * K3];        // all h1 split, FC input (192MB)
__device__ __align__(128) float g_part0[6][BB * 1024];
__device__ __align__(128) float g_part1[12][BB * 1024];
__device__ int g_ctr[2][8];

// ---------------- helpers ----------------
__device__ __forceinline__ void split2(float w, __nv_bfloat16& hi, __nv_bfloat16& lo) {
    hi = __float2bfloat16(w);
    lo = __float2bfloat16(w - __bfloat162float(hi));
}

// 128x128 CTA tile GEMM core: C += A[128,K] * B[128,K]^T, bf16 in, fp32 accum.
// A row-major (lda), B row-major-by-N (ldb, K contiguous) == mma col-major B.
// 256 threads, 8 warps as 2(M)x4(N): warp tile 64x32.
__device__ __forceinline__ void gemm_core(
    const __nv_bfloat16* __restrict__ A, int lda,
    const __nv_bfloat16* __restrict__ B, int ldb,
    int nChunks, __nv_bfloat16* As, __nv_bfloat16* Bs, float acc[4][4][4])
{
    const int tid  = threadIdx.x;
    const int warp = tid >> 5, lane = tid & 31;
    const int gid  = lane >> 2, tig = lane & 3;
    const int wm   = (warp & 1) << 6;   // 0 / 64
    const int wn   = (warp >> 1) << 5;  // 0 / 32 / 64 / 96
    const int r0   = tid >> 2;          // 0..63
    const int s0   = (tid & 3) << 3;    // 0,8,16,24 (halves)

    const __nv_bfloat16* pa0 = A + (size_t)r0 * lda + s0;
    const __nv_bfloat16* pa1 = A + (size_t)(r0 + 64) * lda + s0;
    const __nv_bfloat16* pb0 = B + (size_t)r0 * ldb + s0;
    const __nv_bfloat16* pb1 = B + (size_t)(r0 + 64) * ldb + s0;

    uint4 ra0 = *reinterpret_cast<const uint4*>(pa0);
    uint4 ra1 = *reinterpret_cast<const uint4*>(pa1);
    uint4 rb0 = *reinterpret_cast<const uint4*>(pb0);
    uint4 rb1 = *reinterpret_cast<const uint4*>(pb1);

    const unsigned* Aw = reinterpret_cast<const unsigned*>(As);
    const unsigned* Bw = reinterpret_cast<const unsigned*>(Bs);

    for (int kt = 0; kt < nChunks; ++kt) {
        __syncthreads();
        *reinterpret_cast<uint4*>(As + r0 * 40 + s0)        = ra0;
        *reinterpret_cast<uint4*>(As + (r0 + 64) * 40 + s0) = ra1;
        *reinterpret_cast<uint4*>(Bs + r0 * 40 + s0)        = rb0;
        *reinterpret_cast<uint4*>(Bs + (r0 + 64) * 40 + s0) = rb1;
        __syncthreads();
        if (kt + 1 < nChunks) {
            const int ko = (kt + 1) << 5;
            ra0 = *reinterpret_cast<const uint4*>(pa0 + ko);
            ra1 = *reinterpret_cast<const uint4*>(pa1 + ko);
            rb0 = *reinterpret_cast<const uint4*>(pb0 + ko);
            rb1 = *reinterpret_cast<const uint4*>(pb1 + ko);
        }
#pragma unroll
        for (int ks = 0; ks < 2; ++ks) {
            const int kw = ks << 3;  // word offset for k=0 / k=16
            unsigned af[4][4], bfr[4][2];
#pragma unroll
            for (int mi = 0; mi < 4; ++mi) {
                const int rb = (wm + (mi << 4) + gid) * 20 + kw + tig;
                af[mi][0] = Aw[rb];
                af[mi][1] = Aw[rb + 160];
                af[mi][2] = Aw[rb + 4];
                af[mi][3] = Aw[rb + 164];
            }
#pragma unroll
            for (int ni = 0; ni < 4; ++ni) {
                const int nb = (wn + (ni << 3) + gid) * 20 + kw + tig;
                bfr[ni][0] = Bw[nb];
                bfr[ni][1] = Bw[nb + 4];
            }
#pragma unroll
            for (int mi = 0; mi < 4; ++mi)
#pragma unroll
                for (int ni = 0; ni < 4; ++ni) {
                    asm volatile(
                        "mma.sync.aligned.m16n8k16.row.col.f32.bf16.bf16.f32 "
                        "{%0,%1,%2,%3},{%4,%5,%6,%7},{%8,%9},{%0,%1,%2,%3};\n"
                        : "+f"(acc[mi][ni][0]), "+f"(acc[mi][ni][1]),
                          "+f"(acc[mi][ni][2]), "+f"(acc[mi][ni][3])
                        : "r"(af[mi][0]), "r"(af[mi][1]), "r"(af[mi][2]), "r"(af[mi][3]),
                          "r"(bfr[ni][0]), "r"(bfr[ni][1]));
                }
        }
    }
}

// ---------------- init / prep ----------------
__global__ void init_kernel() {
    int i = blockIdx.x * blockDim.x + threadIdx.x;  // 0..393215
    if (i < BB * K3) {
        g_h0buf[0][i] = __float2bfloat16(0.f);
        g_h1zero[i]   = __float2bfloat16(0.f);
    }
    if (i < 16) reinterpret_cast<int*>(g_ctr)[i] = 0;
}

__global__ void prep_kernel(const float* __restrict__ Whh0,
                            const float* __restrict__ bih0, const float* __restrict__ bhh0,
                            const float* __restrict__ Wih1, const float* __restrict__ Whh1,
                            const float* __restrict__ bih1, const float* __restrict__ bhh1,
                            const float* __restrict__ Wfc)
{
    const int NFC = 4096 * 1024;
    for (int i = blockIdx.x * blockDim.x + threadIdx.x; i < NFC; i += gridDim.x * blockDim.x) {
        int j = i >> 10, k = i & 1023;
        __nv_bfloat16 hi, lo;
        split2(Wfc[i], hi, lo);
        g_Wfcp[(size_t)j * 3072 + k]        = hi;
        g_Wfcp[(size_t)j * 3072 + 1024 + k] = lo;
        g_Wfcp[(size_t)j * 3072 + 2048 + k] = hi;
        if (i < 1024 * 1024) {
            split2(Whh0[i], hi, lo);
            g_W0p[(size_t)j * 3072 + k]        = hi;
            g_W0p[(size_t)j * 3072 + 1024 + k] = lo;
            g_W0p[(size_t)j * 3072 + 2048 + k] = hi;
            split2(Wih1[i], hi, lo);
            g_W1p[(size_t)j * 6144 + k]        = hi;
            g_W1p[(size_t)j * 6144 + 1024 + k] = lo;
            g_W1p[(size_t)j * 6144 + 2048 + k] = hi;
            split2(Whh1[i], hi, lo);
            g_W1p[(size_t)j * 6144 + 3072 + k]        = hi;
            g_W1p[(size_t)j * 6144 + 3072 + 1024 + k] = lo;
            g_W1p[(size_t)j * 6144 + 3072 + 2048 + k] = hi;
        }
        if (i < 1024) {
            g_bias0[i] = bih0[i] + bhh0[i];
            g_bias1[i] = bih1[i] + bhh1[i];
        }
    }
}

// ---------------- recurrence step (pipelined: L0 at t=s, L1 at t=s-1) ----------------
__global__ __launch_bounds__(256) void step_kernel(const float* __restrict__ x,
                                                   const float* __restrict__ Wih0, int s)
{
    __shared__ __align__(16) __nv_bfloat16 As[128 * 40];
    __shared__ __align__(16) __nv_bfloat16 Bs[128 * 40];
    float acc[4][4][4];
#pragma unroll
    for (int a = 0; a < 4; ++a)
#pragma unroll
        for (int b = 0; b < 4; ++b)
#pragma unroll
            for (int c = 0; c < 4; ++c) acc[a][b][c] = 0.f;

    const int bidx = blockIdx.x;
    int layer, tile, split, nsplit, ldb;
    const __nv_bfloat16 *A, *Bp;

    if (bidx < 48) {                 // layer 0: 8 tiles x 6 splits
        if (s == 256) return;
        layer = 0; tile = bidx / 6; split = bidx % 6; nsplit = 6; ldb = 3072;
        A  = g_h0buf[s & 1] + split * 512;
        Bp = g_W0p + (size_t)tile * 128 * 3072 + split * 512;
    } else {                          // layer 1: 8 tiles x 12 splits
        if (s == 0) return;
        layer = 1; const int j = bidx - 48; tile = j / 12; split = j % 12; nsplit = 12; ldb = 6144;
        const int u = s - 1;
        if (split < 6) A = g_h0buf[s & 1] + split * 512;               // h0(t=u)
        else {
            const __nv_bfloat16* hprev = (u == 0) ? g_h1zero : g_H1S[u - 1];
            A = hprev + (split - 6) * 512;                              // h1(t=u-1)
        }
        Bp = g_W1p + (size_t)tile * 128 * 6144 +
             ((split < 6) ? split * 512 : 3072 + (split - 6) * 512);
    }

    gemm_core(A, 3072, Bp, ldb, 16, As, Bs, acc);

    // write partial tile
    float* part = (layer == 0) ? g_part0[split] : g_part1[split];
    {
        const int lane = threadIdx.x & 31, warp = threadIdx.x >> 5;
        const int gid = lane >> 2, tig = lane & 3;
        const int wm = (warp & 1) << 6, wn = (warp >> 1) << 5;
#pragma unroll
        for (int mi = 0; mi < 4; ++mi)
#pragma unroll
            for (int ni = 0; ni < 4; ++ni) {
                const int row = wm + (mi << 4) + gid;
                const int col = tile * 128 + wn + (ni << 3) + 2 * tig;
                *reinterpret_cast<float2*>(&part[row * 1024 + col]) =
                    make_float2(acc[mi][ni][0], acc[mi][ni][1]);
                *reinterpret_cast<float2*>(&part[(row + 8) * 1024 + col]) =
                    make_float2(acc[mi][ni][2], acc[mi][ni][3]);
            }
    }

    __threadfence();
    __shared__ int lastFlag;
    if (threadIdx.x == 0) {
        const int old = atomicAdd(&g_ctr[layer][tile], 1);
        lastFlag = (old == nsplit - 1);
    }
    __syncthreads();
    if (!lastFlag) return;

    // last CTA per tile: reduce + bias (+ rank-1 x*W_ih0 for L0) + tanh + re-split
    if (layer == 0) {
        __nv_bfloat16* dst = g_h0buf[(s + 1) & 1];
        for (int i = threadIdx.x; i < 128 * 128; i += 256) {
            const int b = i >> 7, c = i & 127, g = tile * 128 + c;
            float v = g_bias0[g] + x[b * TT + s] * Wih0[g];
#pragma unroll
            for (int sp = 0; sp < 6; ++sp) v += __ldcg(&g_part0[sp][b * 1024 + g]);
            v = tanhf(v);
            __nv_bfloat16 hi, lo; split2(v, hi, lo);
            dst[b * K3 + g]        = hi;
            dst[b * K3 + 1024 + g] = hi;
            dst[b * K3 + 2048 + g] = lo;
        }
    } else {
        __nv_bfloat16* dst = g_H1S[s - 1];
        for (int i = threadIdx.x; i < 128 * 128; i += 256) {
            const int b = i >> 7, c = i & 127, g = tile * 128 + c;
            float v = g_bias1[g];
#pragma unroll
            for (int sp = 0; sp < 12; ++sp) v += __ldcg(&g_part1[sp][b * 1024 + g]);
            v = tanhf(v);
            __nv_bfloat16 hi, lo; split2(v, hi, lo);
            dst[b * K3 + g]        = hi;
            dst[b * K3 + 1024 + g] = hi;
            dst[b * K3 + 2048 + g] = lo;
        }
    }
    if (threadIdx.x == 0) g_ctr[layer][tile] = 0;  // ready for next launch / replay
}

// ---------------- trailing FC GEMM: out[b,t,v] = h1(t) . Wfc[v] + bfc[v] ----------------
__global__ __launch_bounds__(256) void fc_kernel(const float* __restrict__ bfc,
                                                 float* __restrict__ out)
{
    __shared__ __align__(16) __nv_bfloat16 As[128 * 40];
    __shared__ __align__(16) __nv_bfloat16 Bs[128 * 40];
    float acc[4][4][4];
#pragma unroll
    for (int a = 0; a < 4; ++a)
#pragma unroll
        for (int b = 0; b < 4; ++b)
#pragma unroll
            for (int c = 0; c < 4; ++c) acc[a][b][c] = 0.f;

    const int tn = blockIdx.x;   // 0..31 (V tiles)
    const int t  = blockIdx.y;   // 0..255 (time == M tile)
    const __nv_bfloat16* A  = g_H1S[t];
    const __nv_bfloat16* Bp = g_Wfcp + (size_t)tn * 128 * 3072;

    gemm_core(A, 3072, Bp, 3072, 96, As, Bs, acc);

    const int lane = threadIdx.x & 31, warp = threadIdx.x >> 5;
    const int gid = lane >> 2, tig = lane & 3;
    const int wm = (warp & 1) << 6, wn = (warp >> 1) << 5;
#pragma unroll
    for (int mi = 0; mi < 4; ++mi)
#pragma unroll
        for (int ni = 0; ni < 4; ++ni) {
            const int b   = wm + (mi << 4) + gid;          // batch row
            const int col = tn * 128 + wn + (ni << 3) + 2 * tig;
            const float bv0 = bfc[col], bv1 = bfc[col + 1];
            const size_t o0 = ((size_t)b * TT + t) * VV + col;
            const size_t o1 = ((size_t)(b + 8) * TT + t) * VV + col;
            *reinterpret_cast<float2*>(&out[o0]) =
                make_float2(acc[mi][ni][0] + bv0, acc[mi][ni][1] + bv1);
            *reinterpret_cast<float2*>(&out[o1]) =
                make_float2(acc[mi][ni][2] + bv0, acc[mi][ni][3] + bv1);
        }
}

// ---------------- final hidden states ----------------
__global__ void tail_kernel(float* __restrict__ out) {
    const int i = blockIdx.x * blockDim.x + threadIdx.x;  // 0 .. 2*B*H-1
    if (i >= 2 * BB * HH) return;
    const size_t base = (size_t)BB * TT * VV;
    if (i < BB * HH) {
        const int b = i >> 10, j = i & 1023;
        const __nv_bfloat16* src = g_h0buf[0] + b * K3;   // h0(255) lives in buf 0
        out[base + i] = __bfloat162float(src[j]) + __bfloat162float(src[2048 + j]);
    } else {
        const int k = i - BB * HH;
        const int b = k >> 10, j = k & 1023;
        const __nv_bfloat16* src = g_H1S[TT - 1] + b * K3;
        out[base + i] = __bfloat162float(src[j]) + __bfloat162float(src[2048 + j]);
    }
}

// ---------------- launch ----------------
extern "C" void kernel_launch(void* const* d_in, const int* in_sizes, int n_in,
                              void* d_out, int out_size)
{
    const float* x    = (const float*)d_in[0];
    const float* Wih0 = (const float*)d_in[1];
    const float* Whh0 = (const float*)d_in[2];
    const float* bih0 = (const float*)d_in[3];
    const float* bhh0 = (const float*)d_in[4];
    const float* Wih1 = (const float*)d_in[5];
    const float* Whh1 = (const float*)d_in[6];
    const float* bih1 = (const float*)d_in[7];
    const float* bhh1 = (const float*)d_in[8];
    const float* Wfc  = (const float*)d_in[9];
    const float* bfc  = (const float*)d_in[10];
    float* out = (float*)d_out;

    init_kernel<<<(BB * K3 + 255) / 256, 256>>>();
    prep_kernel<<<2048, 256>>>(Whh0, bih0, bhh0, Wih1, Whh1, bih1, bhh1, Wfc);

    for (int s = 0; s <= TT; ++s)
        step_kernel<<<144, 256>>>(x, Wih0, s);

    fc_kernel<<<dim3(32, 256), 256>>>(bfc, out);

    if (out_size >= BB * TT * VV + 2 * BB * HH)
        tail_kernel<<<(2 * BB * HH + 255) / 256, 256>>>(out);
}

// round 11
// speedup vs baseline: 1.7330x; 1.4195x over previous
#include <cuda_runtime.h>
#include <cuda_bf16.h>
#include <cstdint>

// Problem dims
#define BB 128
#define TT 256
#define HH 1024
#define VV 4096
#define K3 3072          // split-bf16 stacked K (activations [hi|hi|lo])

#define NSTAGE 4
#define STG_HALVES 10240   // per stage: A 5120 halves + B 5120 halves (each 128 rows x 40)
#define SMEM_BYTES (NSTAGE * STG_HALVES * 2)   // 81920

// ---------------- static device scratch ----------------
__device__ __align__(128) __nv_bfloat16 g_W0p[1024 * 3072];   // Whh0 stacked [hi|lo|hi]
__device__ __align__(128) __nv_bfloat16 g_W1p[1024 * 6144];   // [Wih1 stacked | Whh1 stacked]
__device__ __align__(128) __nv_bfloat16 g_Wfcp[4096 * 3072];  // Wfc stacked
__device__ __align__(128) float g_bias0[1024];
__device__ __align__(128) float g_bias1[1024];
__device__ __align__(128) __nv_bfloat16 g_h0buf[2][BB * K3];  // ping-pong h0 stacked
__device__ __align__(128) __nv_bfloat16 g_H1S[TT][BB * K3];   // h1 history (FC input)
__device__ __align__(128) float g_part0[6][BB * 1024];
__device__ __align__(128) float g_part1[12][BB * 1024];
__device__ int g_arr[2][8];   // per (layer,tile) arrivals   (self-reset per launch)
__device__ int g_don[2][8];   // per (layer,tile) reduce-done (self-reset per launch)

// ---------------- helpers ----------------
__device__ __forceinline__ void split2(float w, __nv_bfloat16& hi, __nv_bfloat16& lo) {
    hi = __float2bfloat16(w);
    lo = __float2bfloat16(w - __bfloat162float(hi));
}

__device__ __forceinline__ int ld_acq(const int* p) {
    int v;
    asm volatile("ld.global.acquire.gpu.b32 %0, [%1];" : "=r"(v) : "l"(p) : "memory");
    return v;
}

__device__ __forceinline__ void cp_async16(__nv_bfloat16* dst, const __nv_bfloat16* src) {
    unsigned d = (unsigned)__cvta_generic_to_shared(dst);
    asm volatile("cp.async.cg.shared.global [%0], [%1], 16;\n" :: "r"(d), "l"(src));
}
#define CP_COMMIT() asm volatile("cp.async.commit_group;\n")
#define CP_WAIT2()  asm volatile("cp.async.wait_group 2;\n")

__device__ __forceinline__ unsigned pack_bf2(__nv_bfloat16 a, __nv_bfloat16 b) {
    return ((unsigned)__bfloat16_as_ushort(b) << 16) | (unsigned)__bfloat16_as_ushort(a);
}

// ---- 4-stage cp.async pipelined 128x128 tile GEMM ----
// C += A[128,K]*B[128,K]^T, bf16 in, fp32 acc. 256 thr, 8 warps 2(M)x4(N).
// Requires nChunks >= 3. sm: NSTAGE stages of [A 128x40 | B 128x40] halves.
__device__ __forceinline__ void gemm_pipe(
    const __nv_bfloat16* __restrict__ A, int lda,
    const __nv_bfloat16* __restrict__ B, int ldb,
    int nChunks, __nv_bfloat16* sm, float acc[4][4][4])
{
    const int tid  = threadIdx.x;
    const int warp = tid >> 5, lane = tid & 31;
    const int gid  = lane >> 2, tig = lane & 3;
    const int wm   = (warp & 1) << 6;
    const int wn   = (warp >> 1) << 5;
    const int r0   = tid >> 2;            // 0..63
    const int s0   = (tid & 3) << 3;      // 0,8,16,24 halves

    const __nv_bfloat16* pa0 = A + (size_t)r0 * lda + s0;
    const __nv_bfloat16* pa1 = A + (size_t)(r0 + 64) * lda + s0;
    const __nv_bfloat16* pb0 = B + (size_t)r0 * ldb + s0;
    const __nv_bfloat16* pb1 = B + (size_t)(r0 + 64) * ldb + s0;
    const int d0 = r0 * 40 + s0, d1 = (r0 + 64) * 40 + s0;

    auto issue_body = [&](int kt) {
        __nv_bfloat16* sA = sm + (kt & 3) * STG_HALVES;
        __nv_bfloat16* sB = sA + 5120;
        const int ko = kt << 5;
        cp_async16(sA + d0, pa0 + ko);
        cp_async16(sA + d1, pa1 + ko);
        cp_async16(sB + d0, pb0 + ko);
        cp_async16(sB + d1, pb1 + ko);
    };

#pragma unroll
    for (int p = 0; p < NSTAGE - 1; ++p) { issue_body(p); CP_COMMIT(); }

    for (int kt = 0; kt < nChunks; ++kt) {
        CP_WAIT2();
        __syncthreads();
        if (kt + NSTAGE - 1 < nChunks) issue_body(kt + NSTAGE - 1);
        CP_COMMIT();

        const unsigned* Aw = reinterpret_cast<const unsigned*>(sm + (kt & 3) * STG_HALVES);
        const unsigned* Bw = Aw + 2560;
#pragma unroll
        for (int ks = 0; ks < 2; ++ks) {
            const int kw = ks << 3;
            unsigned af[4][4], bfr[4][2];
#pragma unroll
            for (int mi = 0; mi < 4; ++mi) {
                const int rb = (wm + (mi << 4) + gid) * 20 + kw + tig;
                af[mi][0] = Aw[rb];
                af[mi][1] = Aw[rb + 160];
                af[mi][2] = Aw[rb + 4];
                af[mi][3] = Aw[rb + 164];
            }
#pragma unroll
            for (int ni = 0; ni < 4; ++ni) {
                const int nb = (wn + (ni << 3) + gid) * 20 + kw + tig;
                bfr[ni][0] = Bw[nb];
                bfr[ni][1] = Bw[nb + 4];
            }
#pragma unroll
            for (int mi = 0; mi < 4; ++mi)
#pragma unroll
                for (int ni = 0; ni < 4; ++ni) {
                    asm volatile(
                        "mma.sync.aligned.m16n8k16.row.col.f32.bf16.bf16.f32 "
                        "{%0,%1,%2,%3},{%4,%5,%6,%7},{%8,%9},{%0,%1,%2,%3};\n"
                        : "+f"(acc[mi][ni][0]), "+f"(acc[mi][ni][1]),
                          "+f"(acc[mi][ni][2]), "+f"(acc[mi][ni][3])
                        : "r"(af[mi][0]), "r"(af[mi][1]), "r"(af[mi][2]), "r"(af[mi][3]),
                          "r"(bfr[ni][0]), "r"(bfr[ni][1]));
                }
        }
    }
}

// ---------------- init / prep ----------------
__global__ void init_kernel() {
    const int i = threadIdx.x;
    if (i < 16) {
        reinterpret_cast<int*>(g_arr)[i] = 0;
        reinterpret_cast<int*>(g_don)[i] = 0;
    }
}

__global__ void prep_kernel(const float* __restrict__ Whh0,
                            const float* __restrict__ bih0, const float* __restrict__ bhh0,
                            const float* __restrict__ Wih1, const float* __restrict__ Whh1,
                            const float* __restrict__ bih1, const float* __restrict__ bhh1,
                            const float* __restrict__ Wfc)
{
    const int NFC = 4096 * 1024;
    for (int i = blockIdx.x * blockDim.x + threadIdx.x; i < NFC; i += gridDim.x * blockDim.x) {
        int j = i >> 10, k = i & 1023;
        __nv_bfloat16 hi, lo;
        split2(Wfc[i], hi, lo);
        g_Wfcp[(size_t)j * 3072 + k]        = hi;
        g_Wfcp[(size_t)j * 3072 + 1024 + k] = lo;
        g_Wfcp[(size_t)j * 3072 + 2048 + k] = hi;
        if (i < 1024 * 1024) {
            split2(Whh0[i], hi, lo);
            g_W0p[(size_t)j * 3072 + k]        = hi;
            g_W0p[(size_t)j * 3072 + 1024 + k] = lo;
            g_W0p[(size_t)j * 3072 + 2048 + k] = hi;
            split2(Wih1[i], hi, lo);
            g_W1p[(size_t)j * 6144 + k]        = hi;
            g_W1p[(size_t)j * 6144 + 1024 + k] = lo;
            g_W1p[(size_t)j * 6144 + 2048 + k] = hi;
            split2(Whh1[i], hi, lo);
            g_W1p[(size_t)j * 6144 + 3072 + k]        = hi;
            g_W1p[(size_t)j * 6144 + 3072 + 1024 + k] = lo;
            g_W1p[(size_t)j * 6144 + 3072 + 2048 + k] = hi;
        }
        if (i < 1024) {
            g_bias0[i] = bih0[i] + bhh0[i];
            g_bias1[i] = bih1[i] + bhh1[i];
        }
    }
}

// ---------------- per-step kernel (launch s = 0..256) ----------------
// L0 (CTA 0..47): h0(t=s)   = tanh(x_s*Wih0 + b0 + h0(s-1)@Whh0^T)   [s<256]
// L1 (CTA 48..143): h1(t=s-1) = tanh(h0(s-1)@Wih1^T + b1 + h1(s-2)@Whh1^T) [s>0]
// All cross-step deps are cross-launch (stream-ordered). Within a launch the only
// sync is intra-tile arrive->spin->reduce (co-resident: grid 144 <= 148 SMs).
__global__ void __launch_bounds__(256, 1) step_kernel(const float* __restrict__ x,
                                                      const float* __restrict__ Wih0, int s)
{
    extern __shared__ __align__(16) __nv_bfloat16 sm[];
    const int bidx = blockIdx.x;
    const int tid = threadIdx.x;

    int layer, tile, split, nsplit, ldb;
    bool doG;
    const __nv_bfloat16 *A = nullptr, *Bp = nullptr;

    if (bidx < 48) {
        if (s == 256) return;
        layer = 0; tile = bidx / 6; split = bidx % 6; nsplit = 6; ldb = 3072;
        doG = (s > 0);
        A  = g_h0buf[s & 1] + split * 512;
        Bp = g_W0p + (size_t)tile * 128 * 3072 + split * 512;
    } else {
        if (s == 0) return;
        layer = 1; const int j = bidx - 48; tile = j / 12; split = j % 12; nsplit = 12; ldb = 6144;
        const int u = s - 1;
        if (split < 6) { doG = true; A = g_h0buf[s & 1] + split * 512; }
        else           { doG = (u > 0); if (doG) A = g_H1S[u - 1] + (split - 6) * 512; }
        Bp = g_W1p + (size_t)tile * 128 * 6144 +
             ((split < 6) ? split * 512 : 3072 + (split - 6) * 512);
    }

    float acc[4][4][4];
#pragma unroll
    for (int a = 0; a < 4; ++a)
#pragma unroll
        for (int b = 0; b < 4; ++b)
#pragma unroll
            for (int c = 0; c < 4; ++c) acc[a][b][c] = 0.f;

    if (doG) gemm_pipe(A, 3072, Bp, ldb, 16, sm, acc);

    // write partials (fp32, L2)
    float* part = (layer == 0) ? g_part0[split] : g_part1[split];
    if (doG) {
        const int lane = tid & 31, warp = tid >> 5;
        const int gid = lane >> 2, tig = lane & 3;
        const int wm = (warp & 1) << 6, wn = (warp >> 1) << 5;
#pragma unroll
        for (int mi = 0; mi < 4; ++mi)
#pragma unroll
            for (int ni = 0; ni < 4; ++ni) {
                const int row = wm + (mi << 4) + gid;
                const int col = tile * 128 + wn + (ni << 3) + 2 * tig;
                __stcg(reinterpret_cast<float2*>(&part[row * 1024 + col]),
                       make_float2(acc[mi][ni][0], acc[mi][ni][1]));
                __stcg(reinterpret_cast<float2*>(&part[(row + 8) * 1024 + col]),
                       make_float2(acc[mi][ni][2], acc[mi][ni][3]));
            }
    }
    __threadfence();
    __syncthreads();

    int* arrp = &g_arr[layer][tile];
    int* donp = &g_don[layer][tile];
    if (tid == 0) {
        atomicAdd(arrp, 1);
        while (ld_acq(arrp) < nsplit) {}   // all tile-mates arrived (co-resident)
    }
    __syncthreads();

    // distributed reduce: my row slice of this tile
    const int rb0 = (split * 128) / nsplit, rb1 = ((split + 1) * 128) / nsplit;
    const int nsum = (layer == 0) ? (s > 0 ? 6 : 0) : ((s > 1) ? 12 : 6);
    const float* pbase = (layer == 0) ? &g_part0[0][0] : &g_part1[0][0];
    __nv_bfloat16* dst = (layer == 0) ? g_h0buf[(s + 1) & 1] : g_H1S[s - 1];

    const int nE4 = (rb1 - rb0) * 32;
    for (int idx = tid; idx < nE4; idx += 256) {
        const int b  = rb0 + (idx >> 5);
        const int c4 = (idx & 31) << 2;
        const int g  = tile * 128 + c4;
        float4 v;
        if (layer == 0) {
            const float xv = x[b * TT + s];
            v.x = g_bias0[g]     + xv * Wih0[g];
            v.y = g_bias0[g + 1] + xv * Wih0[g + 1];
            v.z = g_bias0[g + 2] + xv * Wih0[g + 2];
            v.w = g_bias0[g + 3] + xv * Wih0[g + 3];
        } else {
            v = *reinterpret_cast<const float4*>(&g_bias1[g]);
        }
        const float* pb = pbase + b * 1024 + g;
        for (int sp = 0; sp < nsum; ++sp) {
            const float4 t = __ldcg(reinterpret_cast<const float4*>(pb + sp * (BB * 1024)));
            v.x += t.x; v.y += t.y; v.z += t.z; v.w += t.w;
        }
        v.x = tanhf(v.x); v.y = tanhf(v.y); v.z = tanhf(v.z); v.w = tanhf(v.w);
        __nv_bfloat16 h0, l0, h1, l1, h2, l2, h3, l3;
        split2(v.x, h0, l0); split2(v.y, h1, l1);
        split2(v.z, h2, l2); split2(v.w, h3, l3);
        const uint2 whi = make_uint2(pack_bf2(h0, h1), pack_bf2(h2, h3));
        const uint2 wlo = make_uint2(pack_bf2(l0, l1), pack_bf2(l2, l3));
        __nv_bfloat16* dp = dst + (size_t)b * K3 + g;
        *reinterpret_cast<uint2*>(dp)        = whi;   // seg0: hi (x W_hi)
        *reinterpret_cast<uint2*>(dp + 1024) = whi;   // seg1: hi (x W_lo)
        *reinterpret_cast<uint2*>(dp + 2048) = wlo;   // seg2: lo (x W_hi)
    }
    __threadfence();
    __syncthreads();
    if (tid == 0) {
        const int old = atomicAdd(donp, 1);
        if (old == nsplit - 1) {          // last finisher resets for next launch/replay
            *reinterpret_cast<volatile int*>(arrp) = 0;
            __threadfence();
            *reinterpret_cast<volatile int*>(donp) = 0;
        }
    }
}

// ---------------- trailing FC GEMM: out[b,t,v] = h1(t).Wfc[v] + bfc[v] ----------------
__global__ void __launch_bounds__(256, 1) fc_kernel(const float* __restrict__ bfc,
                                                    float* __restrict__ out)
{
    extern __shared__ __align__(16) __nv_bfloat16 sm[];
    float acc[4][4][4];
#pragma unroll
    for (int a = 0; a < 4; ++a)
#pragma unroll
        for (int b = 0; b < 4; ++b)
#pragma unroll
            for (int c = 0; c < 4; ++c) acc[a][b][c] = 0.f;

    const int tn = blockIdx.x;   // 0..31 (V tiles)
    const int t  = blockIdx.y;   // 0..255 (time)
    const __nv_bfloat16* A  = g_H1S[t];
    const __nv_bfloat16* Bp = g_Wfcp + (size_t)tn * 128 * 3072;

    gemm_pipe(A, 3072, Bp, 3072, 96, sm, acc);

    const int lane = threadIdx.x & 31, warp = threadIdx.x >> 5;
    const int gid = lane >> 2, tig = lane & 3;
    const int wm = (warp & 1) << 6, wn = (warp >> 1) << 5;
#pragma unroll
    for (int mi = 0; mi < 4; ++mi)
#pragma unroll
        for (int ni = 0; ni < 4; ++ni) {
            const int b   = wm + (mi << 4) + gid;
            const int col = tn * 128 + wn + (ni << 3) + 2 * tig;
            const float bv0 = bfc[col], bv1 = bfc[col + 1];
            const size_t o0 = ((size_t)b * TT + t) * VV + col;
            const size_t o1 = ((size_t)(b + 8) * TT + t) * VV + col;
            *reinterpret_cast<float2*>(&out[o0]) =
                make_float2(acc[mi][ni][0] + bv0, acc[mi][ni][1] + bv1);
            *reinterpret_cast<float2*>(&out[o1]) =
                make_float2(acc[mi][ni][2] + bv0, acc[mi][ni][3] + bv1);
        }
}

// ---------------- final hidden states ----------------
__global__ void tail_kernel(float* __restrict__ out) {
    const int i = blockIdx.x * blockDim.x + threadIdx.x;
    if (i >= 2 * BB * HH) return;
    const size_t base = (size_t)BB * TT * VV;
    if (i < BB * HH) {
        const int b = i >> 10, j = i & 1023;
        const __nv_bfloat16* src = g_h0buf[0] + (size_t)b * K3;  // h0(255): launch 255 wrote buf (255+1)&1 = 0
        out[base + i] = __bfloat162float(src[j]) + __bfloat162float(src[2048 + j]);
    } else {
        const int k = i - BB * HH;
        const int b = k >> 10, j = k & 1023;
        const __nv_bfloat16* src = g_H1S[TT - 1] + (size_t)b * K3;
        out[base + i] = __bfloat162float(src[j]) + __bfloat162float(src[2048 + j]);
    }
}

// ---------------- launch ----------------
extern "C" void kernel_launch(void* const* d_in, const int* in_sizes, int n_in,
                              void* d_out, int out_size)
{
    const float* x    = (const float*)d_in[0];
    const float* Wih0 = (const float*)d_in[1];
    const float* Whh0 = (const float*)d_in[2];
    const float* bih0 = (const float*)d_in[3];
    const float* bhh0 = (const float*)d_in[4];
    const float* Wih1 = (const float*)d_in[5];
    const float* Whh1 = (const float*)d_in[6];
    const float* bih1 = (const float*)d_in[7];
    const float* bhh1 = (const float*)d_in[8];
    const float* Wfc  = (const float*)d_in[9];
    const float* bfc  = (const float*)d_in[10];
    float* out = (float*)d_out;

    cudaFuncSetAttribute(step_kernel, cudaFuncAttributeMaxDynamicSharedMemorySize, SMEM_BYTES);
    cudaFuncSetAttribute(fc_kernel,   cudaFuncAttributeMaxDynamicSharedMemorySize, SMEM_BYTES);

    init_kernel<<<1, 32>>>();
    prep_kernel<<<2048, 256>>>(Whh0, bih0, bhh0, Wih1, Whh1, bih1, bhh1, Wfc);

    for (int s = 0; s <= TT; ++s)
        step_kernel<<<144, 256, SMEM_BYTES>>>(x, Wih0, s);

    fc_kernel<<<dim3(32, 256), 256, SMEM_BYTES>>>(bfc, out);

    if (out_size >= BB * TT * VV + 2 * BB * HH)
        tail_kernel<<<(2 * BB * HH + 255) / 256, 256>>>(out);
}

// round 12
// speedup vs baseline: 1.9122x; 1.1034x over previous
#include <cuda_runtime.h>
#include <cuda_bf16.h>
#include <cstdint>

// Problem dims
#define BB 128
#define TT 256
#define HH 1024
#define VV 4096
#define K3 3072          // split-bf16 stacked K (activations [hi|hi|lo])

#define NSTAGE 3
#define STG_HALVES 10240   // per stage: A 5120 halves + B 5120 halves (128 rows x 40)
#define SMEM_BYTES (NSTAGE * STG_HALVES * 2)   // 61440

// ---------------- static device scratch ----------------
__device__ __align__(128) __nv_bfloat16 g_W0p[1024 * 3072];   // Whh0 stacked [hi|lo|hi]
__device__ __align__(128) __nv_bfloat16 g_W1p[1024 * 6144];   // [Wih1 stacked | Whh1 stacked]
__device__ __align__(128) __nv_bfloat16 g_Wfcp[4096 * 3072];  // Wfc stacked
__device__ __align__(128) float g_bias0[1024];
__device__ __align__(128) float g_bias1[1024];
__device__ __align__(128) __nv_bfloat16 g_h0buf[2][BB * K3];  // ping-pong h0 stacked
__device__ __align__(128) __nv_bfloat16 g_H1S[TT][BB * K3];   // h1 history (FC input)
__device__ __align__(128) float g_part0[12][BB * 1024];
__device__ __align__(128) float g_part1[24][BB * 1024];
__device__ int g_arr[2][8];   // per (layer,tile) arrivals   (self-reset per launch)
__device__ int g_don[2][8];   // per (layer,tile) reduce-done (self-reset per launch)

// ---------------- helpers ----------------
__device__ __forceinline__ void split2(float w, __nv_bfloat16& hi, __nv_bfloat16& lo) {
    hi = __float2bfloat16(w);
    lo = __float2bfloat16(w - __bfloat162float(hi));
}

__device__ __forceinline__ int ld_acq(const int* p) {
    int v;
    asm volatile("ld.global.acquire.gpu.b32 %0, [%1];" : "=r"(v) : "l"(p) : "memory");
    return v;
}

__device__ __forceinline__ void cp_async16(__nv_bfloat16* dst, const __nv_bfloat16* src) {
    unsigned d = (unsigned)__cvta_generic_to_shared(dst);
    asm volatile("cp.async.cg.shared.global [%0], [%1], 16;\n" :: "r"(d), "l"(src));
}
#define CP_COMMIT() asm volatile("cp.async.commit_group;\n")
#define CP_WAIT1()  asm volatile("cp.async.wait_group 1;\n")

__device__ __forceinline__ unsigned pack_bf2(__nv_bfloat16 a, __nv_bfloat16 b) {
    return ((unsigned)__bfloat16_as_ushort(b) << 16) | (unsigned)__bfloat16_as_ushort(a);
}

// ---- 3-stage cp.async pipelined 128x128 tile GEMM ----
// C += A[128,K]*B[128,K]^T, bf16 in, fp32 acc. 256 thr, 8 warps 2(M)x4(N).
// Requires nChunks >= 2. sm: NSTAGE stages of [A 128x40 | B 128x40] halves.
__device__ __forceinline__ void gemm_pipe(
    const __nv_bfloat16* __restrict__ A, int lda,
    const __nv_bfloat16* __restrict__ B, int ldb,
    int nChunks, __nv_bfloat16* sm, float acc[4][4][4])
{
    const int tid  = threadIdx.x;
    const int warp = tid >> 5, lane = tid & 31;
    const int gid  = lane >> 2, tig = lane & 3;
    const int wm   = (warp & 1) << 6;
    const int wn   = (warp >> 1) << 5;
    const int r0   = tid >> 2;            // 0..63
    const int s0   = (tid & 3) << 3;      // 0,8,16,24 halves

    const __nv_bfloat16* pa0 = A + (size_t)r0 * lda + s0;
    const __nv_bfloat16* pa1 = A + (size_t)(r0 + 64) * lda + s0;
    const __nv_bfloat16* pb0 = B + (size_t)r0 * ldb + s0;
    const __nv_bfloat16* pb1 = B + (size_t)(r0 + 64) * ldb + s0;
    const int d0 = r0 * 40 + s0, d1 = (r0 + 64) * 40 + s0;

    auto issue_body = [&](int kt) {
        __nv_bfloat16* sA = sm + (kt % NSTAGE) * STG_HALVES;
        __nv_bfloat16* sB = sA + 5120;
        const int ko = kt << 5;
        cp_async16(sA + d0, pa0 + ko);
        cp_async16(sA + d1, pa1 + ko);
        cp_async16(sB + d0, pb0 + ko);
        cp_async16(sB + d1, pb1 + ko);
    };

#pragma unroll
    for (int p = 0; p < NSTAGE - 1; ++p) { issue_body(p); CP_COMMIT(); }

    for (int kt = 0; kt < nChunks; ++kt) {
        CP_WAIT1();
        __syncthreads();
        if (kt + NSTAGE - 1 < nChunks) issue_body(kt + NSTAGE - 1);
        CP_COMMIT();

        const unsigned* Aw = reinterpret_cast<const unsigned*>(sm + (kt % NSTAGE) * STG_HALVES);
        const unsigned* Bw = Aw + 2560;
#pragma unroll
        for (int ks = 0; ks < 2; ++ks) {
            const int kw = ks << 3;
            unsigned af[4][4], bfr[4][2];
#pragma unroll
            for (int mi = 0; mi < 4; ++mi) {
                const int rb = (wm + (mi << 4) + gid) * 20 + kw + tig;
                af[mi][0] = Aw[rb];
                af[mi][1] = Aw[rb + 160];
                af[mi][2] = Aw[rb + 4];
                af[mi][3] = Aw[rb + 164];
            }
#pragma unroll
            for (int ni = 0; ni < 4; ++ni) {
                const int nb = (wn + (ni << 3) + gid) * 20 + kw + tig;
                bfr[ni][0] = Bw[nb];
                bfr[ni][1] = Bw[nb + 4];
            }
#pragma unroll
            for (int mi = 0; mi < 4; ++mi)
#pragma unroll
                for (int ni = 0; ni < 4; ++ni) {
                    asm volatile(
                        "mma.sync.aligned.m16n8k16.row.col.f32.bf16.bf16.f32 "
                        "{%0,%1,%2,%3},{%4,%5,%6,%7},{%8,%9},{%0,%1,%2,%3};\n"
                        : "+f"(acc[mi][ni][0]), "+f"(acc[mi][ni][1]),
                          "+f"(acc[mi][ni][2]), "+f"(acc[mi][ni][3])
                        : "r"(af[mi][0]), "r"(af[mi][1]), "r"(af[mi][2]), "r"(af[mi][3]),
                          "r"(bfr[ni][0]), "r"(bfr[ni][1]));
                }
        }
    }
}

// ---------------- init / prep ----------------
__global__ void init_kernel() {
    const int i = threadIdx.x;
    if (i < 16) {
        reinterpret_cast<int*>(g_arr)[i] = 0;
        reinterpret_cast<int*>(g_don)[i] = 0;
    }
}

__global__ void prep_kernel(const float* __restrict__ Whh0,
                            const float* __restrict__ bih0, const float* __restrict__ bhh0,
                            const float* __restrict__ Wih1, const float* __restrict__ Whh1,
                            const float* __restrict__ bih1, const float* __restrict__ bhh1,
                            const float* __restrict__ Wfc)
{
    const int NFC = 4096 * 1024;
    for (int i = blockIdx.x * blockDim.x + threadIdx.x; i < NFC; i += gridDim.x * blockDim.x) {
        int j = i >> 10, k = i & 1023;
        __nv_bfloat16 hi, lo;
        split2(Wfc[i], hi, lo);
        g_Wfcp[(size_t)j * 3072 + k]        = hi;
        g_Wfcp[(size_t)j * 3072 + 1024 + k] = lo;
        g_Wfcp[(size_t)j * 3072 + 2048 + k] = hi;
        if (i < 1024 * 1024) {
            split2(Whh0[i], hi, lo);
            g_W0p[(size_t)j * 3072 + k]        = hi;
            g_W0p[(size_t)j * 3072 + 1024 + k] = lo;
            g_W0p[(size_t)j * 3072 + 2048 + k] = hi;
            split2(Wih1[i], hi, lo);
            g_W1p[(size_t)j * 6144 + k]        = hi;
            g_W1p[(size_t)j * 6144 + 1024 + k] = lo;
            g_W1p[(size_t)j * 6144 + 2048 + k] = hi;
            split2(Whh1[i], hi, lo);
            g_W1p[(size_t)j * 6144 + 3072 + k]        = hi;
            g_W1p[(size_t)j * 6144 + 3072 + 1024 + k] = lo;
            g_W1p[(size_t)j * 6144 + 3072 + 2048 + k] = hi;
        }
        if (i < 1024) {
            g_bias0[i] = bih0[i] + bhh0[i];
            g_bias1[i] = bih1[i] + bhh1[i];
        }
    }
}

// ---------------- per-step kernel (launch s = 0..256) ----------------
// L0 (CTA 0..95):   tile=cta/12, split=cta%12 (K=256 each); h0(t=s), s<256
// L1 (CTA 96..287): tile=/24,    split=%24    (K=256 each); h1(t=s-1), s>0
// grid 288 @ 2 CTAs/SM (smem 60KB, regs<=128) -> all co-resident (296 slots).
// Only sync: intra-tile arrive->spin->reduce; every CTA arrives before spinning.
__global__ void __launch_bounds__(256, 2) step_kernel(const float* __restrict__ x,
                                                      const float* __restrict__ Wih0, int s)
{
    extern __shared__ __align__(16) __nv_bfloat16 sm[];
    const int bidx = blockIdx.x;
    const int tid = threadIdx.x;

    int layer, tile, split, nsplit, ldb;
    bool doG;
    const __nv_bfloat16 *A = nullptr, *Bp = nullptr;

    if (bidx < 96) {
        if (s == 256) return;
        layer = 0; tile = bidx / 12; split = bidx % 12; nsplit = 12; ldb = 3072;
        doG = (s > 0);
        A  = g_h0buf[s & 1] + split * 256;
        Bp = g_W0p + (size_t)tile * 128 * 3072 + split * 256;
    } else {
        if (s == 0) return;
        layer = 1; const int j = bidx - 96; tile = j / 24; split = j % 24; nsplit = 24; ldb = 6144;
        const int u = s - 1;
        if (split < 12) { doG = true; A = g_h0buf[s & 1] + split * 256; }
        else            { doG = (u > 0); if (doG) A = g_H1S[u - 1] + (split - 12) * 256; }
        Bp = g_W1p + (size_t)tile * 128 * 6144 +
             ((split < 12) ? split * 256 : 3072 + (split - 12) * 256);
    }

    float acc[4][4][4];
#pragma unroll
    for (int a = 0; a < 4; ++a)
#pragma unroll
        for (int b = 0; b < 4; ++b)
#pragma unroll
            for (int c = 0; c < 4; ++c) acc[a][b][c] = 0.f;

    if (doG) gemm_pipe(A, 3072, Bp, ldb, 8, sm, acc);

    // write partials (fp32, L2)
    float* part = (layer == 0) ? g_part0[split] : g_part1[split];
    if (doG) {
        const int lane = tid & 31, warp = tid >> 5;
        const int gid = lane >> 2, tig = lane & 3;
        const int wm = (warp & 1) << 6, wn = (warp >> 1) << 5;
#pragma unroll
        for (int mi = 0; mi < 4; ++mi)
#pragma unroll
            for (int ni = 0; ni < 4; ++ni) {
                const int row = wm + (mi << 4) + gid;
                const int col = tile * 128 + wn + (ni << 3) + 2 * tig;
                __stcg(reinterpret_cast<float2*>(&part[row * 1024 + col]),
                       make_float2(acc[mi][ni][0], acc[mi][ni][1]));
                __stcg(reinterpret_cast<float2*>(&part[(row + 8) * 1024 + col]),
                       make_float2(acc[mi][ni][2], acc[mi][ni][3]));
            }
    }
    __threadfence();
    __syncthreads();

    int* arrp = &g_arr[layer][tile];
    int* donp = &g_don[layer][tile];
    if (tid == 0) {
        atomicAdd(arrp, 1);
        while (ld_acq(arrp) < nsplit) {}   // all tile-mates arrived (co-resident)
    }
    __syncthreads();

    // distributed reduce: my row slice of this tile
    const int rb0 = (split * 128) / nsplit, rb1 = ((split + 1) * 128) / nsplit;
    const int nsum = (layer == 0) ? (s > 0 ? 12 : 0) : ((s > 1) ? 24 : 12);
    const float* pbase = (layer == 0) ? &g_part0[0][0] : &g_part1[0][0];
    __nv_bfloat16* dst = (layer == 0) ? g_h0buf[(s + 1) & 1] : g_H1S[s - 1];

    const int nE4 = (rb1 - rb0) * 32;
    for (int idx = tid; idx < nE4; idx += 256) {
        const int b  = rb0 + (idx >> 5);
        const int c4 = (idx & 31) << 2;
        const int g  = tile * 128 + c4;
        float4 v;
        if (layer == 0) {
            const float xv = x[b * TT + s];
            v.x = g_bias0[g]     + xv * Wih0[g];
            v.y = g_bias0[g + 1] + xv * Wih0[g + 1];
            v.z = g_bias0[g + 2] + xv * Wih0[g + 2];
            v.w = g_bias0[g + 3] + xv * Wih0[g + 3];
        } else {
            v = *reinterpret_cast<const float4*>(&g_bias1[g]);
        }
        const float* pb = pbase + b * 1024 + g;
        for (int sp = 0; sp < nsum; ++sp) {
            const float4 t = __ldcg(reinterpret_cast<const float4*>(pb + sp * (BB * 1024)));
            v.x += t.x; v.y += t.y; v.z += t.z; v.w += t.w;
        }
        v.x = tanhf(v.x); v.y = tanhf(v.y); v.z = tanhf(v.z); v.w = tanhf(v.w);
        __nv_bfloat16 h0, l0, h1, l1, h2, l2, h3, l3;
        split2(v.x, h0, l0); split2(v.y, h1, l1);
        split2(v.z, h2, l2); split2(v.w, h3, l3);
        const uint2 whi = make_uint2(pack_bf2(h0, h1), pack_bf2(h2, h3));
        const uint2 wlo = make_uint2(pack_bf2(l0, l1), pack_bf2(l2, l3));
        __nv_bfloat16* dp = dst + (size_t)b * K3 + g;
        *reinterpret_cast<uint2*>(dp)        = whi;   // seg0: hi (x W_hi)
        *reinterpret_cast<uint2*>(dp + 1024) = whi;   // seg1: hi (x W_lo)
        *reinterpret_cast<uint2*>(dp + 2048) = wlo;   // seg2: lo (x W_hi)
    }
    __threadfence();
    __syncthreads();
    if (tid == 0) {
        const int old = atomicAdd(donp, 1);
        if (old == nsplit - 1) {          // last finisher resets for next launch/replay
            *reinterpret_cast<volatile int*>(arrp) = 0;
            __threadfence();
            *reinterpret_cast<volatile int*>(donp) = 0;
        }
    }
}

// ---------------- trailing FC GEMM: out[b,t,v] = h1(t).Wfc[v] + bfc[v] ----------------
__global__ void __launch_bounds__(256, 2) fc_kernel(const float* __restrict__ bfc,
                                                    float* __restrict__ out)
{
    extern __shared__ __align__(16) __nv_bfloat16 sm[];
    float acc[4][4][4];
#pragma unroll
    for (int a = 0; a < 4; ++a)
#pragma unroll
        for (int b = 0; b < 4; ++b)
#pragma unroll
            for (int c = 0; c < 4; ++c) acc[a][b][c] = 0.f;

    const int tn = blockIdx.x;   // 0..31 (V tiles)
    const int t  = blockIdx.y;   // 0..255 (time)
    const __nv_bfloat16* A  = g_H1S[t];
    const __nv_bfloat16* Bp = g_Wfcp + (size_t)tn * 128 * 3072;

    gemm_pipe(A, 3072, Bp, 3072, 96, sm, acc);

    const int lane = threadIdx.x & 31, warp = threadIdx.x >> 5;
    const int gid = lane >> 2, tig = lane & 3;
    const int wm = (warp & 1) << 6, wn = (warp >> 1) << 5;
#pragma unroll
    for (int mi = 0; mi < 4; ++mi)
#pragma unroll
        for (int ni = 0; ni < 4; ++ni) {
            const int b   = wm + (mi << 4) + gid;
            const int col = tn * 128 + wn + (ni << 3) + 2 * tig;
            const float bv0 = bfc[col], bv1 = bfc[col + 1];
            const size_t o0 = ((size_t)b * TT + t) * VV + col;
            const size_t o1 = ((size_t)(b + 8) * TT + t) * VV + col;
            *reinterpret_cast<float2*>(&out[o0]) =
                make_float2(acc[mi][ni][0] + bv0, acc[mi][ni][1] + bv1);
            *reinterpret_cast<float2*>(&out[o1]) =
                make_float2(acc[mi][ni][2] + bv0, acc[mi][ni][3] + bv1);
        }
}

// ---------------- final hidden states ----------------
__global__ void tail_kernel(float* __restrict__ out) {
    const int i = blockIdx.x * blockDim.x + threadIdx.x;
    if (i >= 2 * BB * HH) return;
    const size_t base = (size_t)BB * TT * VV;
    if (i < BB * HH) {
        const int b = i >> 10, j = i & 1023;
        const __nv_bfloat16* src = g_h0buf[0] + (size_t)b * K3;  // h0(255) in buf (255+1)&1 = 0
        out[base + i] = __bfloat162float(src[j]) + __bfloat162float(src[2048 + j]);
    } else {
        const int k = i - BB * HH;
        const int b = k >> 10, j = k & 1023;
        const __nv_bfloat16* src = g_H1S[TT - 1] + (size_t)b * K3;
        out[base + i] = __bfloat162float(src[j]) + __bfloat162float(src[2048 + j]);
    }
}

// ---------------- launch ----------------
extern "C" void kernel_launch(void* const* d_in, const int* in_sizes, int n_in,
                              void* d_out, int out_size)
{
    const float* x    = (const float*)d_in[0];
    const float* Wih0 = (const float*)d_in[1];
    const float* Whh0 = (const float*)d_in[2];
    const float* bih0 = (const float*)d_in[3];
    const float* bhh0 = (const float*)d_in[4];
    const float* Wih1 = (const float*)d_in[5];
    const float* Whh1 = (const float*)d_in[6];
    const float* bih1 = (const float*)d_in[7];
    const float* bhh1 = (const float*)d_in[8];
    const float* Wfc  = (const float*)d_in[9];
    const float* bfc  = (const float*)d_in[10];
    float* out = (float*)d_out;

    cudaFuncSetAttribute(step_kernel, cudaFuncAttributeMaxDynamicSharedMemorySize, SMEM_BYTES);
    cudaFuncSetAttribute(fc_kernel,   cudaFuncAttributeMaxDynamicSharedMemorySize, SMEM_BYTES);

    init_kernel<<<1, 32>>>();
    prep_kernel<<<2048, 256>>>(Whh0, bih0, bhh0, Wih1, Whh1, bih1, bhh1, Wfc);

    for (int s = 0; s <= TT; ++s)
        step_kernel<<<288, 256, SMEM_BYTES>>>(x, Wih0, s);

    fc_kernel<<<dim3(32, 256), 256, SMEM_BYTES>>>(bfc, out);

    if (out_size >= BB * TT * VV + 2 * BB * HH)
        tail_kernel<<<(2 * BB * HH + 255) / 256, 256>>>(out);
}

// round 13
// speedup vs baseline: 2.0919x; 1.0940x over previous
#include <cuda_runtime.h>
#include <cuda_bf16.h>
#include <cstdint>

// Problem dims
#define BB 128
#define TT 256
#define HH 1024
#define VV 4096
#define K3 3072          // split-bf16 stacked K (activations [hi|hi|lo])

#define NSTAGE 3
#define STG_HALVES 10240   // per stage: A 5120 halves + B 5120 halves (128 rows x 40)
#define SMEM_BYTES (NSTAGE * STG_HALVES * 2)   // 61440

// ---------------- static device scratch ----------------
__device__ __align__(128) __nv_bfloat16 g_W0p[1024 * 3072];   // Whh0 stacked [hi|lo|hi]
__device__ __align__(128) __nv_bfloat16 g_W1p[1024 * 6144];   // [Wih1 stacked | Whh1 stacked]
__device__ __align__(128) __nv_bfloat16 g_Wfcp[4096 * 3072];  // Wfc stacked
__device__ __align__(128) float g_bias0[1024];
__device__ __align__(128) float g_bias1[1024];
__device__ __align__(128) __nv_bfloat16 g_h0buf[2][BB * K3];  // ping-pong h0 stacked
__device__ __align__(128) __nv_bfloat16 g_H1S[TT][BB * K3];   // h1 history (FC input)
__device__ __align__(128) float g_part0[12][BB * 1024];
__device__ __align__(128) float g_part1[24][BB * 1024];
__device__ int g_arr[2][8];   // per (layer,tile) arrivals: MONOTONIC across launches,
                              // reset once per kernel_launch by init_kernel.

// ---------------- helpers ----------------
__device__ __forceinline__ void split2(float w, __nv_bfloat16& hi, __nv_bfloat16& lo) {
    hi = __float2bfloat16(w);
    lo = __float2bfloat16(w - __bfloat162float(hi));
}

__device__ __forceinline__ int ld_acq(const int* p) {
    int v;
    asm volatile("ld.global.acquire.gpu.b32 %0, [%1];" : "=r"(v) : "l"(p) : "memory");
    return v;
}

// Release-arrive: publishes all prior writes of the CTA (writes -> __syncthreads()
// -> tid0 release) to any thread that acquire-reads the counter. Replaces
// __threadfence() + relaxed atomicAdd (two fewer GPU-scope membars per CTA).
__device__ __forceinline__ void red_add_release(int* p, int v) {
    asm volatile("red.global.add.release.gpu.s32 [%0], %1;" :: "l"(p), "r"(v) : "memory");
}

__device__ __forceinline__ void cp_async16(__nv_bfloat16* dst, const __nv_bfloat16* src) {
    unsigned d = (unsigned)__cvta_generic_to_shared(dst);
    asm volatile("cp.async.cg.shared.global [%0], [%1], 16;\n" :: "r"(d), "l"(src));
}
#define CP_COMMIT() asm volatile("cp.async.commit_group;\n")
#define CP_WAIT1()  asm volatile("cp.async.wait_group 1;\n")

__device__ __forceinline__ unsigned pack_bf2(__nv_bfloat16 a, __nv_bfloat16 b) {
    return ((unsigned)__bfloat16_as_ushort(b) << 16) | (unsigned)__bfloat16_as_ushort(a);
}

// ---- 3-stage cp.async pipelined 128x128 tile GEMM ----
// C += A[128,K]*B[128,K]^T, bf16 in, fp32 acc. 256 thr, 8 warps 2(M)x4(N).
// Requires nChunks >= 2. sm: NSTAGE stages of [A 128x40 | B 128x40] halves.
__device__ __forceinline__ void gemm_pipe(
    const __nv_bfloat16* __restrict__ A, int lda,
    const __nv_bfloat16* __restrict__ B, int ldb,
    int nChunks, __nv_bfloat16* sm, float acc[4][4][4])
{
    const int tid  = threadIdx.x;
    const int warp = tid >> 5, lane = tid & 31;
    const int gid  = lane >> 2, tig = lane & 3;
    const int wm   = (warp & 1) << 6;
    const int wn   = (warp >> 1) << 5;
    const int r0   = tid >> 2;            // 0..63
    const int s0   = (tid & 3) << 3;      // 0,8,16,24 halves

    const __nv_bfloat16* pa0 = A + (size_t)r0 * lda + s0;
    const __nv_bfloat16* pa1 = A + (size_t)(r0 + 64) * lda + s0;
    const __nv_bfloat16* pb0 = B + (size_t)r0 * ldb + s0;
    const __nv_bfloat16* pb1 = B + (size_t)(r0 + 64) * ldb + s0;
    const int d0 = r0 * 40 + s0, d1 = (r0 + 64) * 40 + s0;

    auto issue_body = [&](int kt) {
        __nv_bfloat16* sA = sm + (kt % NSTAGE) * STG_HALVES;
        __nv_bfloat16* sB = sA + 5120;
        const int ko = kt << 5;
        cp_async16(sA + d0, pa0 + ko);
        cp_async16(sA + d1, pa1 + ko);
        cp_async16(sB + d0, pb0 + ko);
        cp_async16(sB + d1, pb1 + ko);
    };

#pragma unroll
    for (int p = 0; p < NSTAGE - 1; ++p) { issue_body(p); CP_COMMIT(); }

    for (int kt = 0; kt < nChunks; ++kt) {
        CP_WAIT1();
        __syncthreads();
        if (kt + NSTAGE - 1 < nChunks) issue_body(kt + NSTAGE - 1);
        CP_COMMIT();

        const unsigned* Aw = reinterpret_cast<const unsigned*>(sm + (kt % NSTAGE) * STG_HALVES);
        const unsigned* Bw = Aw + 2560;
#pragma unroll
        for (int ks = 0; ks < 2; ++ks) {
            const int kw = ks << 3;
            unsigned af[4][4], bfr[4][2];
#pragma unroll
            for (int mi = 0; mi < 4; ++mi) {
                const int rb = (wm + (mi << 4) + gid) * 20 + kw + tig;
                af[mi][0] = Aw[rb];
                af[mi][1] = Aw[rb + 160];
                af[mi][2] = Aw[rb + 4];
                af[mi][3] = Aw[rb + 164];
            }
#pragma unroll
            for (int ni = 0; ni < 4; ++ni) {
                const int nb = (wn + (ni << 3) + gid) * 20 + kw + tig;
                bfr[ni][0] = Bw[nb];
                bfr[ni][1] = Bw[nb + 4];
            }
#pragma unroll
            for (int mi = 0; mi < 4; ++mi)
#pragma unroll
                for (int ni = 0; ni < 4; ++ni) {
                    asm volatile(
                        "mma.sync.aligned.m16n8k16.row.col.f32.bf16.bf16.f32 "
                        "{%0,%1,%2,%3},{%4,%5,%6,%7},{%8,%9},{%0,%1,%2,%3};\n"
                        : "+f"(acc[mi][ni][0]), "+f"(acc[mi][ni][1]),
                          "+f"(acc[mi][ni][2]), "+f"(acc[mi][ni][3])
                        : "r"(af[mi][0]), "r"(af[mi][1]), "r"(af[mi][2]), "r"(af[mi][3]),
                          "r"(bfr[ni][0]), "r"(bfr[ni][1]));
                }
        }
    }
}

// ---------------- init / prep ----------------
__global__ void init_kernel() {
    const int i = threadIdx.x;
    if (i < 16) reinterpret_cast<int*>(g_arr)[i] = 0;
}

__global__ void prep_kernel(const float* __restrict__ Whh0,
                            const float* __restrict__ bih0, const float* __restrict__ bhh0,
                            const float* __restrict__ Wih1, const float* __restrict__ Whh1,
                            const float* __restrict__ bih1, const float* __restrict__ bhh1,
                            const float* __restrict__ Wfc)
{
    const int NFC = 4096 * 1024;
    for (int i = blockIdx.x * blockDim.x + threadIdx.x; i < NFC; i += gridDim.x * blockDim.x) {
        int j = i >> 10, k = i & 1023;
        __nv_bfloat16 hi, lo;
        split2(Wfc[i], hi, lo);
        g_Wfcp[(size_t)j * 3072 + k]        = hi;
        g_Wfcp[(size_t)j * 3072 + 1024 + k] = lo;
        g_Wfcp[(size_t)j * 3072 + 2048 + k] = hi;
        if (i < 1024 * 1024) {
            split2(Whh0[i], hi, lo);
            g_W0p[(size_t)j * 3072 + k]        = hi;
            g_W0p[(size_t)j * 3072 + 1024 + k] = lo;
            g_W0p[(size_t)j * 3072 + 2048 + k] = hi;
            split2(Wih1[i], hi, lo);
            g_W1p[(size_t)j * 6144 + k]        = hi;
            g_W1p[(size_t)j * 6144 + 1024 + k] = lo;
            g_W1p[(size_t)j * 6144 + 2048 + k] = hi;
            split2(Whh1[i], hi, lo);
            g_W1p[(size_t)j * 6144 + 3072 + k]        = hi;
            g_W1p[(size_t)j * 6144 + 3072 + 1024 + k] = lo;
            g_W1p[(size_t)j * 6144 + 3072 + 2048 + k] = hi;
        }
        if (i < 1024) {
            g_bias0[i] = bih0[i] + bhh0[i];
            g_bias1[i] = bih1[i] + bhh1[i];
        }
    }
}

// ---------------- per-step kernel (launch s = 0..256) ----------------
// L0 (CTA 0..95):   tile=cta/12, split=cta%12 (K=256 each); h0(t=s), s<256
// L1 (CTA 96..287): tile=/24,    split=%24    (K=256 each); h1(t=s-1), s>0
// Cross-step deps are cross-launch (stream-ordered; also covers partial-buffer
// WAR, so no done-counter needed). Only intra-launch sync: intra-tile
// release-arrive -> acquire-spin on a MONOTONIC counter (target = f(s)).
// grid 288 @ 2 CTAs/SM -> all co-resident; every CTA arrives before spinning.
__global__ void __launch_bounds__(256, 2) step_kernel(const float* __restrict__ x,
                                                      const float* __restrict__ Wih0, int s)
{
    extern __shared__ __align__(16) __nv_bfloat16 sm[];
    const int bidx = blockIdx.x;
    const int tid = threadIdx.x;

    int layer, tile, split, nsplit, ldb, tgt;
    bool doG;
    const __nv_bfloat16 *A = nullptr, *Bp = nullptr;

    if (bidx < 96) {
        if (s == 256) return;
        layer = 0; tile = bidx / 12; split = bidx % 12; nsplit = 12; ldb = 3072;
        tgt = 12 * (s + 1);                   // L0 arrivals happen in launches 0..s
        doG = (s > 0);
        A  = g_h0buf[s & 1] + split * 256;
        Bp = g_W0p + (size_t)tile * 128 * 3072 + split * 256;
    } else {
        if (s == 0) return;
        layer = 1; const int j = bidx - 96; tile = j / 24; split = j % 24; nsplit = 24; ldb = 6144;
        tgt = 24 * s;                         // L1 arrivals happen in launches 1..s
        const int u = s - 1;
        if (split < 12) { doG = true; A = g_h0buf[s & 1] + split * 256; }
        else            { doG = (u > 0); if (doG) A = g_H1S[u - 1] + (split - 12) * 256; }
        Bp = g_W1p + (size_t)tile * 128 * 6144 +
             ((split < 12) ? split * 256 : 3072 + (split - 12) * 256);
    }

    float acc[4][4][4];
#pragma unroll
    for (int a = 0; a < 4; ++a)
#pragma unroll
        for (int b = 0; b < 4; ++b)
#pragma unroll
            for (int c = 0; c < 4; ++c) acc[a][b][c] = 0.f;

    if (doG) gemm_pipe(A, 3072, Bp, ldb, 8, sm, acc);

    // write partials (fp32, L2)
    float* part = (layer == 0) ? g_part0[split] : g_part1[split];
    if (doG) {
        const int lane = tid & 31, warp = tid >> 5;
        const int gid = lane >> 2, tig = lane & 3;
        const int wm = (warp & 1) << 6, wn = (warp >> 1) << 5;
#pragma unroll
        for (int mi = 0; mi < 4; ++mi)
#pragma unroll
            for (int ni = 0; ni < 4; ++ni) {
                const int row = wm + (mi << 4) + gid;
                const int col = tile * 128 + wn + (ni << 3) + 2 * tig;
                __stcg(reinterpret_cast<float2*>(&part[row * 1024 + col]),
                       make_float2(acc[mi][ni][0], acc[mi][ni][1]));
                __stcg(reinterpret_cast<float2*>(&part[(row + 8) * 1024 + col]),
                       make_float2(acc[mi][ni][2], acc[mi][ni][3]));
            }
    }
    __syncthreads();                          // all CTA writes done

    int* arrp = &g_arr[layer][tile];
    if (tid == 0) {
        red_add_release(arrp, 1);             // publish partials + arrive
        while (ld_acq(arrp) < tgt) {}         // all tile-mates arrived (co-resident)
    }
    __syncthreads();                          // broadcast acquire to whole CTA

    // distributed reduce: my row slice of this tile
    const int rb0 = (split * 128) / nsplit, rb1 = ((split + 1) * 128) / nsplit;
    const int nsum = (layer == 0) ? (s > 0 ? 12 : 0) : ((s > 1) ? 24 : 12);
    const float* pbase = (layer == 0) ? &g_part0[0][0] : &g_part1[0][0];
    __nv_bfloat16* dst = (layer == 0) ? g_h0buf[(s + 1) & 1] : g_H1S[s - 1];

    const int nE4 = (rb1 - rb0) * 32;
    for (int idx = tid; idx < nE4; idx += 256) {
        const int b  = rb0 + (idx >> 5);
        const int c4 = (idx & 31) << 2;
        const int g  = tile * 128 + c4;
        float4 v;
        if (layer == 0) {
            const float xv = x[b * TT + s];
            v.x = g_bias0[g]     + xv * Wih0[g];
            v.y = g_bias0[g + 1] + xv * Wih0[g + 1];
            v.z = g_bias0[g + 2] + xv * Wih0[g + 2];
            v.w = g_bias0[g + 3] + xv * Wih0[g + 3];
        } else {
            v = *reinterpret_cast<const float4*>(&g_bias1[g]);
        }
        const float* pb = pbase + b * 1024 + g;
        for (int sp = 0; sp < nsum; ++sp) {
            const float4 t = __ldcg(reinterpret_cast<const float4*>(pb + sp * (BB * 1024)));
            v.x += t.x; v.y += t.y; v.z += t.z; v.w += t.w;
        }
        v.x = tanhf(v.x); v.y = tanhf(v.y); v.z = tanhf(v.z); v.w = tanhf(v.w);
        __nv_bfloat16 h0, l0, h1, l1, h2, l2, h3, l3;
        split2(v.x, h0, l0); split2(v.y, h1, l1);
        split2(v.z, h2, l2); split2(v.w, h3, l3);
        const uint2 whi = make_uint2(pack_bf2(h0, h1), pack_bf2(h2, h3));
        const uint2 wlo = make_uint2(pack_bf2(l0, l1), pack_bf2(l2, l3));
        __nv_bfloat16* dp = dst + (size_t)b * K3 + g;
        *reinterpret_cast<uint2*>(dp)        = whi;   // seg0: hi (x W_hi)
        *reinterpret_cast<uint2*>(dp + 1024) = whi;   // seg1: hi (x W_lo)
        *reinterpret_cast<uint2*>(dp + 2048) = wlo;   // seg2: lo (x W_hi)
    }
    // No trailing fence/counter: next launch is stream-ordered behind this one.
}

// ---------------- trailing FC GEMM: out[b,t,v] = h1(t).Wfc[v] + bfc[v] ----------------
__global__ void __launch_bounds__(256, 2) fc_kernel(const float* __restrict__ bfc,
                                                    float* __restrict__ out)
{
    extern __shared__ __align__(16) __nv_bfloat16 sm[];
    float acc[4][4][4];
#pragma unroll
    for (int a = 0; a < 4; ++a)
#pragma unroll
        for (int b = 0; b < 4; ++b)
#pragma unroll
            for (int c = 0; c < 4; ++c) acc[a][b][c] = 0.f;

    const int tn = blockIdx.x;   // 0..31 (V tiles)
    const int t  = blockIdx.y;   // 0..255 (time)
    const __nv_bfloat16* A  = g_H1S[t];
    const __nv_bfloat16* Bp = g_Wfcp + (size_t)tn * 128 * 3072;

    gemm_pipe(A, 3072, Bp, 3072, 96, sm, acc);

    const int lane = threadIdx.x & 31, warp = threadIdx.x >> 5;
    const int gid = lane >> 2, tig = lane & 3;
    const int wm = (warp & 1) << 6, wn = (warp >> 1) << 5;
#pragma unroll
    for (int mi = 0; mi < 4; ++mi)
#pragma unroll
        for (int ni = 0; ni < 4; ++ni) {
            const int b   = wm + (mi << 4) + gid;
            const int col = tn * 128 + wn + (ni << 3) + 2 * tig;
            const float bv0 = bfc[col], bv1 = bfc[col + 1];
            const size_t o0 = ((size_t)b * TT + t) * VV + col;
            const size_t o1 = ((size_t)(b + 8) * TT + t) * VV + col;
            *reinterpret_cast<float2*>(&out[o0]) =
                make_float2(acc[mi][ni][0] + bv0, acc[mi][ni][1] + bv1);
            *reinterpret_cast<float2*>(&out[o1]) =
                make_float2(acc[mi][ni][2] + bv0, acc[mi][ni][3] + bv1);
        }
}

// ---------------- final hidden states ----------------
__global__ void tail_kernel(float* __restrict__ out) {
    const int i = blockIdx.x * blockDim.x + threadIdx.x;
    if (i >= 2 * BB * HH) return;
    const size_t base = (size_t)BB * TT * VV;
    if (i < BB * HH) {
        const int b = i >> 10, j = i & 1023;
        const __nv_bfloat16* src = g_h0buf[0] + (size_t)b * K3;  // h0(255) in buf (255+1)&1 = 0
        out[base + i] = __bfloat162float(src[j]) + __bfloat162float(src[2048 + j]);
    } else {
        const int k = i - BB * HH;
        const int b = k >> 10, j = k & 1023;
        const __nv_bfloat16* src = g_H1S[TT - 1] + (size_t)b * K3;
        out[base + i] = __bfloat162float(src[j]) + __bfloat162float(src[2048 + j]);
    }
}

// ---------------- launch ----------------
extern "C" void kernel_launch(void* const* d_in, const int* in_sizes, int n_in,
                              void* d_out, int out_size)
{
    const float* x    = (const float*)d_in[0];
    const float* Wih0 = (const float*)d_in[1];
    const float* Whh0 = (const float*)d_in[2];
    const float* bih0 = (const float*)d_in[3];
    const float* bhh0 = (const float*)d_in[4];
    const float* Wih1 = (const float*)d_in[5];
    const float* Whh1 = (const float*)d_in[6];
    const float* bih1 = (const float*)d_in[7];
    const float* bhh1 = (const float*)d_in[8];
    const float* Wfc  = (const float*)d_in[9];
    const float* bfc  = (const float*)d_in[10];
    float* out = (float*)d_out;

    cudaFuncSetAttribute(step_kernel, cudaFuncAttributeMaxDynamicSharedMemorySize, SMEM_BYTES);
    cudaFuncSetAttribute(fc_kernel,   cudaFuncAttributeMaxDynamicSharedMemorySize, SMEM_BYTES);

    init_kernel<<<1, 32>>>();
    prep_kernel<<<2048, 256>>>(Whh0, bih0, bhh0, Wih1, Whh1, bih1, bhh1, Wfc);

    for (int s = 0; s <= TT; ++s)
        step_kernel<<<288, 256, SMEM_BYTES>>>(x, Wih0, s);

    fc_kernel<<<dim3(32, 256), 256, SMEM_BYTES>>>(bfc, out);

    if (out_size >= BB * TT * VV + 2 * BB * HH)
        tail_kernel<<<(2 * BB * HH + 255) / 256, 256>>>(out);
}